// round 3
// baseline (speedup 1.0000x reference)
#include <cuda_runtime.h>
#include <cstddef>

#define ALPHA_ 0.0001f
#define NN 16
#define TT 8
#define VV 256
#define FF 64
#define NVV (NN*VV*VV)
#define YS 68               // padded row stride: conflict-free column reads
#define NBLK 128

__device__ float g_sloss[NBLK];
__device__ float g_dloss[NN];
__device__ unsigned int g_counter = 0;

__device__ __forceinline__ unsigned long long addx2(unsigned long long a,
                                                    unsigned long long b) {
    unsigned long long r;
    asm("add.rn.f32x2 %0, %1, %2;" : "=l"(r) : "l"(a), "l"(b));
    return r;
}
__device__ __forceinline__ float2 unpack2(unsigned long long v) {
    float2 r;
    asm("mov.b64 {%0, %1}, %2;" : "=f"(r.x), "=f"(r.y) : "l"(v));
    return r;
}

// grid (8 j-tiles, 16 n), 1024 threads = 32 warps, 8 warps/SMSP.
// Warp w handles i in [8w, 8w+8); lane owns column j = jt*32 + lane.
// Feature dim processed in 2 halves of 32 so -xj fits in 32 regs (<=64 total).
extern "C" __global__ void __launch_bounds__(1024, 1)
fused_kernel(const float* __restrict__ x, const float* __restrict__ a,
             float* __restrict__ out) {
    extern __shared__ float y[];            // VV * YS floats (~68 KB)
    __shared__ float red[1024];
    __shared__ float sxp[1024];
    __shared__ float sqw[32];
    __shared__ float cs[32];
    __shared__ float wsum[32];

    const int tid  = threadIdx.x;
    const int lane = tid & 31;
    const int w    = tid >> 5;
    const int n    = blockIdx.y;
    const int jt   = blockIdx.x;
    const float* __restrict__ xm = x + (size_t)(n * TT + TT / 2) * (VV * FF);

    // Stage y = xm * a. tid%64 is a FIXED feature index -> per-f raw sums free.
    const int   f  = tid & 63;
    const float af = __ldg(&a[f]);
    float Sx = 0.f, Sq = 0.f;
#pragma unroll
    for (int k = 0; k < 16; ++k) {
        int idx = tid + (k << 10);
        float v = xm[idx];
        y[(idx >> 6) * YS + f] = v * af;
        Sx += v;
        Sq = fmaf(v, v, Sq);
    }
    sxp[tid] = Sx;
#pragma unroll
    for (int o = 16; o; o >>= 1) Sq += __shfl_down_sync(~0u, Sq, o);
    if (lane == 0) sqw[w] = Sq;
    __syncthreads();

    // dloss_n = 2*(V*sum x^2 - sum_f (sum_i x)^2); valid because S's column
    // sums are exactly 1 (softmax axis) so sum(S@d2) == sum(d2).
    if (jt == 0 && w == 0) {
        float s1 = 0.f, s2 = 0.f;
#pragma unroll
        for (int r = 0; r < 16; ++r) {
            s1 += sxp[lane + (r << 6)];
            s2 += sxp[lane + 32 + (r << 6)];
        }
        float t  = s1 * s1 + s2 * s2;
        float sq = sqw[lane];
#pragma unroll
        for (int o = 16; o; o >>= 1) {
            t  += __shfl_down_sync(~0u, t, o);
            sq += __shfl_down_sync(~0u, sq, o);
        }
        if (lane == 0) __stcg(&g_dloss[n], 2.f * ((float)VV * sq - t));
    }

    const int j     = jt * 32 + lane;
    const int ibase = w << 3;
    const unsigned long long M   = 0x7fffffff7fffffffULL;
    const unsigned long long SGN = 0x8000000080000000ULL;

    float tmp[8];
#pragma unroll
    for (int g = 0; g < 8; ++g) tmp[g] = 0.f;

#pragma unroll
    for (int h = 0; h < 2; ++h) {
        // -xj half (16 u64 = 32 regs); neg via sign XOR (alu pipe, once/half).
        unsigned long long nxj[16];
        const ulonglong2* __restrict__ xjp =
            reinterpret_cast<const ulonglong2*>(&y[j * YS + (h << 5)]);
#pragma unroll
        for (int q = 0; q < 8; ++q) {
            ulonglong2 v = xjp[q];               // conflict-free (stride 272B)
            nxj[2 * q]     = v.x ^ SGN;
            nxj[2 * q + 1] = v.y ^ SGN;
        }
#pragma unroll
        for (int g = 0; g < 8; ++g) {
            const ulonglong2* __restrict__ xi =
                reinterpret_cast<const ulonglong2*>(&y[(ibase + g) * YS + (h << 5)]);
            unsigned long long a0 = 0, a1 = 0;
#pragma unroll
            for (int q = 0; q < 8; ++q) {
                ulonglong2 p = xi[q];            // broadcast LDS.128
                a0 = addx2(a0, addx2(p.x, nxj[2 * q])     & M);
                a1 = addx2(a1, addx2(p.y, nxj[2 * q + 1]) & M);
            }
            float2 u = unpack2(addx2(a0, a1));
            tmp[g] += u.x + u.y;
        }
    }

    // exp (scores >= 0 always: relu is identity) + column partials.
    float colpart = 0.f;
#pragma unroll
    for (int g = 0; g < 8; ++g) {
        float e = __expf(tmp[g]);
        tmp[g] = e;
        colpart += e;
    }

    red[tid] = colpart;
    __syncthreads();
    if (tid < 32) {
        float s = 0.f;
#pragma unroll
        for (int ww = 0; ww < 32; ++ww) s += red[ww * 32 + tid];
        cs[tid] = s;
    }
    __syncthreads();
    const float inv = 1.0f / cs[lane];

    // Write S (coalesced) + accumulate S^2.
    float sq2 = 0.f;
    float* ocol = out + (size_t)n * (VV * VV) + jt * 32 + lane;
#pragma unroll
    for (int g = 0; g < 8; ++g) {
        float Sv = tmp[g] * inv;
        ocol[(size_t)(ibase + g) * VV] = Sv;
        sq2 = fmaf(Sv, Sv, sq2);
    }
#pragma unroll
    for (int o = 16; o; o >>= 1) sq2 += __shfl_down_sync(~0u, sq2, o);
    if (lane == 0) wsum[w] = sq2;
    __syncthreads();

    // Last-block finalize (graph-safe: counter reset each call).
    __shared__ unsigned int s_flag;
    const int bid = n * 8 + jt;
    if (tid == 0) {
        float t = 0.f;
#pragma unroll
        for (int k = 0; k < 32; ++k) t += wsum[k];
        __stcg(&g_sloss[bid], t);
        __threadfence();
        unsigned int c = atomicAdd(&g_counter, 1u);
        s_flag = (c == NBLK - 1) ? 1u : 0u;
    }
    __syncthreads();
    if (s_flag && w == 0) {
        __threadfence();
        float s = 0.f;
#pragma unroll
        for (int k = 0; k < 4; ++k) s += __ldcg(&g_sloss[lane + (k << 5)]);
        float dl = (lane < 16) ? __ldcg(&g_dloss[lane]) : 0.f;
#pragma unroll
        for (int o = 16; o; o >>= 1) {
            s  += __shfl_down_sync(~0u, s, o);
            dl += __shfl_down_sync(~0u, dl, o);
        }
        if (lane == 0) {
            out[NVV]     = s * (ALPHA_ / (float)NN);
            out[NVV + 1] = dl * ALPHA_;
            g_counter = 0;
        }
    }
}

extern "C" void kernel_launch(void* const* d_in, const int* in_sizes, int n_in,
                              void* d_out, int out_size) {
    const float* x = (const float*)d_in[0];
    const float* a = (const float*)d_in[1];
    if (n_in >= 2 && in_sizes[0] == FF) {      // defensive input-order check
        const float* t = x; x = a; a = t;
    }
    float* out = (float*)d_out;

    const int smem = VV * YS * (int)sizeof(float);
    cudaFuncSetAttribute(fused_kernel,
                         cudaFuncAttributeMaxDynamicSharedMemorySize, smem);
    fused_kernel<<<dim3(8, NN), 1024, smem>>>(x, a, out);
}

// round 4
// speedup vs baseline: 1.0171x; 1.0171x over previous
#include <cuda_runtime.h>
#include <cstddef>

#define ALPHA_ 0.0001f
#define NN 16
#define TT 8
#define VV 256
#define FF 64
#define NVV (NN*VV*VV)
#define YS 68               // padded row stride (floats): conflict-free, 16B-aligned rows
#define NBLK 128

__device__ float g_sloss[NBLK];
__device__ float g_dloss[NN];
__device__ unsigned int g_counter = 0;

typedef unsigned long long u64;

__device__ __forceinline__ u64 addx2(u64 a, u64 b) {
    u64 r;
    asm("add.rn.f32x2 %0, %1, %2;" : "=l"(r) : "l"(a), "l"(b));
    return r;
}
__device__ __forceinline__ float2 unpack2(u64 v) {
    float2 r;
    asm("mov.b64 {%0, %1}, %2;" : "=f"(r.x), "=f"(r.y) : "l"(v));
    return r;
}

// grid (8 j-tiles, 16 n), 1024 threads = 32 warps (8/SMSP).
// Warp w: rows i in [8w, 8w+8). Lane: column j = jt*32 + lane.
// Features processed in 4 chunks of 16 -> nxj is only 16 regs; acc64[8]
// persistent packed accumulators; all LDS offsets compile-time immediates.
extern "C" __global__ void __launch_bounds__(1024, 1)
fused_kernel(const float* __restrict__ x, const float* __restrict__ a,
             float* __restrict__ out) {
    extern __shared__ float y[];            // VV * YS floats (~68 KB)
    __shared__ float red[1024];             // reused: Sx partials, then colsum tree
    __shared__ float sqw[32];
    __shared__ float cs[32];
    __shared__ float wsum[32];

    const int tid  = threadIdx.x;
    const int lane = tid & 31;
    const int w    = tid >> 5;
    const int n    = blockIdx.y;
    const int jt   = blockIdx.x;
    const float* __restrict__ xm = x + (size_t)(n * TT + TT / 2) * (VV * FF);

    // Stage y = xm * a. tid&63 is a FIXED feature index -> raw per-f sums free.
    const int   f  = tid & 63;
    const float af = __ldg(&a[f]);
    float Sx = 0.f, Sq = 0.f;
#pragma unroll
    for (int k = 0; k < 16; ++k) {
        int idx = tid + (k << 10);
        float v = xm[idx];
        y[(idx >> 6) * YS + f] = v * af;
        Sx += v;
        Sq = fmaf(v, v, Sq);
    }
    red[tid] = Sx;
#pragma unroll
    for (int o = 16; o; o >>= 1) Sq += __shfl_down_sync(~0u, Sq, o);
    if (lane == 0) sqw[w] = Sq;
    __syncthreads();

    // dloss_n = 2*(V*sum x^2 - sum_f (sum_i x)^2); valid because S's column
    // sums are exactly 1 (softmax axis) so sum(S@d2) == sum(d2).
    if (jt == 0 && w == 0) {
        float s1 = 0.f, s2 = 0.f;
#pragma unroll
        for (int r = 0; r < 16; ++r) {
            s1 += red[lane + (r << 6)];
            s2 += red[lane + 32 + (r << 6)];
        }
        float t  = s1 * s1 + s2 * s2;
        float sq = sqw[lane];
#pragma unroll
        for (int o = 16; o; o >>= 1) {
            t  += __shfl_down_sync(~0u, t, o);
            sq += __shfl_down_sync(~0u, sq, o);
        }
        if (lane == 0) __stcg(&g_dloss[n], 2.f * ((float)VV * sq - t));
    }

    const int j = jt * 32 + lane;
    const float* __restrict__ xjb = &y[j * YS];           // thread base
    const float* __restrict__ xib = &y[(w << 3) * YS];    // warp base
    const u64 M   = 0x7fffffff7fffffffULL;
    const u64 SGN = 0x8000000080000000ULL;

    u64 acc[8];
#pragma unroll
    for (int g = 0; g < 8; ++g) acc[g] = 0;

#pragma unroll
    for (int h = 0; h < 4; ++h) {
        // -xj chunk: 16 floats = 8 u64 = 16 regs.
        u64 nxj[8];
        {
            const ulonglong2* __restrict__ p =
                reinterpret_cast<const ulonglong2*>(xjb + h * 16);
            ulonglong2 v0 = p[0], v1 = p[1], v2 = p[2], v3 = p[3];
            nxj[0] = v0.x ^ SGN; nxj[1] = v0.y ^ SGN;
            nxj[2] = v1.x ^ SGN; nxj[3] = v1.y ^ SGN;
            nxj[4] = v2.x ^ SGN; nxj[5] = v2.y ^ SGN;
            nxj[6] = v3.x ^ SGN; nxj[7] = v3.y ^ SGN;
        }
#pragma unroll
        for (int g = 0; g < 8; ++g) {
            const ulonglong2* __restrict__ xi =
                reinterpret_cast<const ulonglong2*>(xib + g * YS + h * 16);
            ulonglong2 q0 = xi[0], q1 = xi[1], q2 = xi[2], q3 = xi[3];  // broadcast
            u64 d0 = addx2(q0.x, nxj[0]) & M;
            u64 d1 = addx2(q0.y, nxj[1]) & M;
            u64 d2 = addx2(q1.x, nxj[2]) & M;
            u64 d3 = addx2(q1.y, nxj[3]) & M;
            u64 d4 = addx2(q2.x, nxj[4]) & M;
            u64 d5 = addx2(q2.y, nxj[5]) & M;
            u64 d6 = addx2(q3.x, nxj[6]) & M;
            u64 d7 = addx2(q3.y, nxj[7]) & M;
            u64 t = addx2(addx2(addx2(d0, d1), addx2(d2, d3)),
                          addx2(addx2(d4, d5), addx2(d6, d7)));
            acc[g] = addx2(acc[g], t);
        }
    }

    // exp (scores >= 0 always: relu is identity) + column partials.
    float tmp[8];
    float colpart = 0.f;
#pragma unroll
    for (int g = 0; g < 8; ++g) {
        float2 u = unpack2(acc[g]);
        float e  = __expf(u.x + u.y);
        tmp[g] = e;
        colpart += e;
    }

    __syncthreads();                 // red[] reuse barrier
    red[tid] = colpart;
    __syncthreads();
    if (tid < 32) {
        float s = 0.f;
#pragma unroll
        for (int ww = 0; ww < 32; ++ww) s += red[ww * 32 + tid];
        cs[tid] = s;
    }
    __syncthreads();
    const float inv = 1.0f / cs[lane];

    // Write S (coalesced) + accumulate S^2.
    float sq2 = 0.f;
    float* ocol = out + (size_t)n * (VV * VV) + jt * 32 + lane;
#pragma unroll
    for (int g = 0; g < 8; ++g) {
        float Sv = tmp[g] * inv;
        ocol[(size_t)((w << 3) + g) * VV] = Sv;
        sq2 = fmaf(Sv, Sv, sq2);
    }
#pragma unroll
    for (int o = 16; o; o >>= 1) sq2 += __shfl_down_sync(~0u, sq2, o);
    if (lane == 0) wsum[w] = sq2;
    __syncthreads();

    // Last-block finalize (graph-safe: counter reset each call).
    __shared__ unsigned int s_flag;
    const int bid = n * 8 + jt;
    if (tid == 0) {
        float t = 0.f;
#pragma unroll
        for (int k = 0; k < 32; ++k) t += wsum[k];
        __stcg(&g_sloss[bid], t);
        __threadfence();
        unsigned int c = atomicAdd(&g_counter, 1u);
        s_flag = (c == NBLK - 1) ? 1u : 0u;
    }
    __syncthreads();
    if (s_flag && w == 0) {
        __threadfence();
        float s = 0.f;
#pragma unroll
        for (int k = 0; k < 4; ++k) s += __ldcg(&g_sloss[lane + (k << 5)]);
        float dl = (lane < 16) ? __ldcg(&g_dloss[lane]) : 0.f;
#pragma unroll
        for (int o = 16; o; o >>= 1) {
            s  += __shfl_down_sync(~0u, s, o);
            dl += __shfl_down_sync(~0u, dl, o);
        }
        if (lane == 0) {
            out[NVV]     = s * (ALPHA_ / (float)NN);
            out[NVV + 1] = dl * ALPHA_;
            g_counter = 0;
        }
    }
}

extern "C" void kernel_launch(void* const* d_in, const int* in_sizes, int n_in,
                              void* d_out, int out_size) {
    const float* x = (const float*)d_in[0];
    const float* a = (const float*)d_in[1];
    if (n_in >= 2 && in_sizes[0] == FF) {      // defensive input-order check
        const float* t = x; x = a; a = t;
    }
    float* out = (float*)d_out;

    const int smem = VV * YS * (int)sizeof(float);
    cudaFuncSetAttribute(fused_kernel,
                         cudaFuncAttributeMaxDynamicSharedMemorySize, smem);
    fused_kernel<<<dim3(8, NN), 1024, smem>>>(x, a, out);
}